// round 5
// baseline (speedup 1.0000x reference)
#include <cuda_runtime.h>
#include <cstdint>

// Problem shape (fixed per metadata): query [512,32,256], context [512,2048,256]
// out [512*32, 2048] fp32.
#define TB    256
#define OT    16      // O rows per CTA (O=32 split into 2 CTAs)
#define NT    512     // R chunk
#define KT    16      // K tile
#define RD    2048    // R
#define DD    256     // D
#define CPAD  516     // padded row length (floats) for transposed C tile

// shared memory layout (floats)
#define SMEM_S_OFF 0                         // scores [OT][RD]      = 32768 floats
#define SMEM_Q_OFF (OT*RD)                   // Qt [DD][OT]          =  4096 floats
#define SMEM_C_OFF (SMEM_Q_OFF + DD*OT)      // Ct [2][KT][CPAD]     = 16512 floats
#define SMEM_FLOATS (SMEM_C_OFF + 2*KT*CPAD)
#define SMEM_BYTES (SMEM_FLOATS * 4)         // 213504 B <= 227 KB

static_assert(SMEM_BYTES <= 232448, "smem too big");

__device__ __forceinline__ uint64_t pack_dup(float x) {
    uint64_t r;
    asm("mov.b64 %0, {%1, %1};" : "=l"(r) : "f"(x));
    return r;
}
__device__ __forceinline__ void fma2(uint64_t& d, uint64_t a, uint64_t b) {
    asm("fma.rn.f32x2 %0, %1, %2, %0;" : "+l"(d) : "l"(a), "l"(b));
}
__device__ __forceinline__ void unpack2(uint64_t v, float& lo, float& hi) {
    asm("mov.b64 {%0, %1}, %2;" : "=f"(lo), "=f"(hi) : "l"(v));
}

__global__ __launch_bounds__(TB, 1)
void ruleattn_kernel(const float* __restrict__ q,
                     const float* __restrict__ ctx,
                     float* __restrict__ out) {
    extern __shared__ float smem[];
    float* sS  = smem + SMEM_S_OFF;   // scores [OT][RD]
    float* sQt = smem + SMEM_Q_OFF;   // Q transposed [DD][OT]
    float* sC  = smem + SMEM_C_OFF;   // C transposed tiles [2][KT][CPAD]

    const int tid = threadIdx.x;
    const int b   = blockIdx.y;
    const int o0  = blockIdx.x * OT;

    // ---- load Q transposed: sQt[d][m] = q[b][o0+m][d]; tid = d (DD==TB) ----
    {
        const float* qb = q + ((size_t)b * 32 + o0) * DD;
        #pragma unroll
        for (int j = 0; j < OT; ++j)
            sQt[tid * OT + j] = qb[j * DD + tid];
    }

    const int mgrp = tid >> 7;        // 0..1
    const int ngrp = tid & 127;       // 0..127
    const int m0   = mgrp * 8;
    const int n0   = ngrp * 4;
    const int half = tid & 1;
    const int rowb = tid >> 1;        // 0..127

    const float* cb = ctx + (size_t)b * RD * DD;

    __syncthreads();

    // ================= GEMM: scores[OT][RD] = Q @ C^T =================
    for (int chunk = 0; chunk < RD / NT; ++chunk) {
        const int r0 = chunk * NT;

        uint64_t acc[16];   // 4 m-pairs x 4 n, f32x2 over (m, m+1)
        #pragma unroll
        for (int i = 0; i < 16; ++i) acc[i] = 0ull;

        float4 st[4][2];
        // prefetch k-tile 0
        {
            const float* cbase = cb + (size_t)r0 * DD + half * 4;
            #pragma unroll
            for (int j = 0; j < 4; ++j)
                #pragma unroll
                for (int c = 0; c < 2; ++c)
                    st[j][c] = *(const float4*)(cbase + (rowb + 128 * j) * DD + c * 8);
        }

        for (int kt = 0; kt < DD / KT; ++kt) {
            float* bp = sC + (kt & 1) * (KT * CPAD);
            // store staged tile transposed: bp[k][n]
            #pragma unroll
            for (int j = 0; j < 4; ++j) {
                const int n = rowb + 128 * j;
                #pragma unroll
                for (int c = 0; c < 2; ++c) {
                    const int kl = half * 4 + c * 8;
                    bp[(kl + 0) * CPAD + n] = st[j][c].x;
                    bp[(kl + 1) * CPAD + n] = st[j][c].y;
                    bp[(kl + 2) * CPAD + n] = st[j][c].z;
                    bp[(kl + 3) * CPAD + n] = st[j][c].w;
                }
            }
            __syncthreads();

            // prefetch next k-tile while computing this one
            if (kt + 1 < DD / KT) {
                const float* cbase = cb + (size_t)r0 * DD + (kt + 1) * KT + half * 4;
                #pragma unroll
                for (int j = 0; j < 4; ++j)
                    #pragma unroll
                    for (int c = 0; c < 2; ++c)
                        st[j][c] = *(const float4*)(cbase + (rowb + 128 * j) * DD + c * 8);
            }

            // compute KT k-steps (A index advances with the k-tile: d = kt*KT + k)
            const float* aq = sQt + kt * KT * OT;
            #pragma unroll
            for (int k = 0; k < KT; ++k) {
                ulonglong2 A0 = *(const ulonglong2*)(aq + k * OT + m0);     // (m0..m0+3)
                ulonglong2 A1 = *(const ulonglong2*)(aq + k * OT + m0 + 4); // (m0+4..m0+7)
                float4 bv = *(const float4*)(bp + k * CPAD + n0);
                uint64_t b0 = pack_dup(bv.x), b1 = pack_dup(bv.y);
                uint64_t b2 = pack_dup(bv.z), b3 = pack_dup(bv.w);
                fma2(acc[0],  A0.x, b0); fma2(acc[1],  A0.x, b1);
                fma2(acc[2],  A0.x, b2); fma2(acc[3],  A0.x, b3);
                fma2(acc[4],  A0.y, b0); fma2(acc[5],  A0.y, b1);
                fma2(acc[6],  A0.y, b2); fma2(acc[7],  A0.y, b3);
                fma2(acc[8],  A1.x, b0); fma2(acc[9],  A1.x, b1);
                fma2(acc[10], A1.x, b2); fma2(acc[11], A1.x, b3);
                fma2(acc[12], A1.y, b0); fma2(acc[13], A1.y, b1);
                fma2(acc[14], A1.y, b2); fma2(acc[15], A1.y, b3);
            }
            __syncthreads();
        }

        // write accumulators to score smem (vector stores, lane-contiguous)
        #pragma unroll
        for (int mp = 0; mp < 4; ++mp) {
            float4 lo4, hi4;
            unpack2(acc[mp * 4 + 0], lo4.x, hi4.x);
            unpack2(acc[mp * 4 + 1], lo4.y, hi4.y);
            unpack2(acc[mp * 4 + 2], lo4.z, hi4.z);
            unpack2(acc[mp * 4 + 3], lo4.w, hi4.w);
            *(float4*)(sS + (size_t)(m0 + 2 * mp)     * RD + r0 + n0) = lo4;
            *(float4*)(sS + (size_t)(m0 + 2 * mp + 1) * RD + r0 + n0) = hi4;
        }
    }
    __syncthreads();

    // ================= Sparsemax: one warp per row, Newton on tau =================
    const int w    = tid >> 5;
    const int lane = tid & 31;

    #pragma unroll
    for (int p = 0; p < 2; ++p) {
        const int m = w * 2 + p;
        const float4* row4 = (const float4*)(sS + (size_t)m * RD);

        // row max
        float vmax = -1e30f;
        #pragma unroll
        for (int i = 0; i < RD / 4 / 32; ++i) {
            float4 v = row4[lane + 32 * i];
            vmax = fmaxf(vmax, fmaxf(fmaxf(v.x, v.y), fmaxf(v.z, v.w)));
        }
        #pragma unroll
        for (int s = 16; s; s >>= 1)
            vmax = fmaxf(vmax, __shfl_xor_sync(0xffffffffu, vmax, s));

        // Newton from below on f(tau) = sum(relu(z - tau)) - 1 (convex, piecewise-linear,
        // monotone convergence, exact in finitely many steps; typically 1-3 here)
        float tau = vmax - 1.0f;
        for (int it = 0; it < 48; ++it) {
            float S = 0.0f;
            int cnt = 0;
            #pragma unroll
            for (int i = 0; i < RD / 4 / 32; ++i) {
                float4 v = row4[lane + 32 * i];
                float d;
                d = v.x - tau; if (d > 0.0f) { S += d; cnt++; }
                d = v.y - tau; if (d > 0.0f) { S += d; cnt++; }
                d = v.z - tau; if (d > 0.0f) { S += d; cnt++; }
                d = v.w - tau; if (d > 0.0f) { S += d; cnt++; }
            }
            #pragma unroll
            for (int s = 16; s; s >>= 1) {
                S   += __shfl_xor_sync(0xffffffffu, S, s);
                cnt += __shfl_xor_sync(0xffffffffu, cnt, s);
            }
            if (cnt == 0) break;   // paranoia (cannot happen with tau < max)
            float delta = (S - 1.0f) / (float)cnt;
            if (!(delta > 1e-7f * fmaxf(fabsf(tau), 1.0f))) break;
            tau += delta;
        }

        // weights = relu(z - tau), coalesced float4 store
        float4* orow = (float4*)(out + ((size_t)(b * 32 + o0 + m)) * RD);
        #pragma unroll
        for (int i = 0; i < RD / 4 / 32; ++i) {
            float4 v = row4[lane + 32 * i];
            float4 o;
            o.x = fmaxf(v.x - tau, 0.0f);
            o.y = fmaxf(v.y - tau, 0.0f);
            o.z = fmaxf(v.z - tau, 0.0f);
            o.w = fmaxf(v.w - tau, 0.0f);
            orow[lane + 32 * i] = o;
        }
    }
}

extern "C" void kernel_launch(void* const* d_in, const int* in_sizes, int n_in,
                              void* d_out, int out_size) {
    (void)n_in; (void)out_size;
    const float* q   = (const float*)d_in[0];
    const float* ctx = (const float*)d_in[1];
    float* out = (float*)d_out;

    const int B = in_sizes[0] / (32 * DD);   // 512

    cudaFuncSetAttribute(ruleattn_kernel,
                         cudaFuncAttributeMaxDynamicSharedMemorySize, SMEM_BYTES);

    dim3 grid(2, B);
    ruleattn_kernel<<<grid, TB, SMEM_BYTES>>>(q, ctx, out);
}

// round 6
// speedup vs baseline: 1.7026x; 1.7026x over previous
#include <cuda_runtime.h>
#include <cstdint>

// query [512,32,256], context [512,2048,256], out [16384,2048] fp32.
#define DD   256
#define RD   2048
#define NT   256      // N-chunk per CTA (pass 1)
#define KT   16       // K tile
#define CPAD 260      // padded transposed C row (260 mod 8 == 4 -> conflict-free transpose)
#define QPAD 36       // padded Qt row (mult of 4 for LDS.128 alignment)

#define QT_FLOATS (DD * QPAD)          // 9216
#define U_FLOATS  (2 * KT * CPAD)      // 8320  (also holds 8192-float Q staging)
#define P1_SMEM_BYTES ((QT_FLOATS + U_FLOATS) * 4)   // 70144 B -> 3 CTAs/SM

__device__ __forceinline__ uint64_t pack_dup(float x) {
    uint64_t r;
    asm("mov.b64 %0, {%1, %1};" : "=l"(r) : "f"(x));
    return r;
}
__device__ __forceinline__ void fma2(uint64_t& d, uint64_t a, uint64_t b) {
    asm("fma.rn.f32x2 %0, %1, %2, %0;" : "+l"(d) : "l"(a), "l"(b));
}
__device__ __forceinline__ void unpack2(uint64_t v, float& lo, float& hi) {
    asm("mov.b64 {%0, %1}, %2;" : "=f"(lo), "=f"(hi) : "l"(v));
}

// ===================== Pass 1: scores = Q @ C^T -> out ======================
// CTA: 128 threads, tile 32m x 256n, thread tile 8m x 8n (m-paired f32x2).
__global__ __launch_bounds__(128, 3)
void gemm_kernel(const float* __restrict__ q,
                 const float* __restrict__ ctx,
                 float* __restrict__ out) {
    extern __shared__ float smem[];
    float* Qt = smem;              // [DD][QPAD] : Qt[k][m]
    float* U  = smem + QT_FLOATS;  // union: Q staging (8192 f) / C double buffer

    const int tid = threadIdx.x;
    const int b   = blockIdx.y;
    const int r0  = blockIdx.x * NT;

    // ---- stage Q [32][256] coalesced into U ----
    {
        const float* qb = q + (size_t)b * 32 * DD;
        #pragma unroll
        for (int it = 0; it < 16; ++it) {
            int i = (tid + 128 * it) * 4;
            *(float4*)(U + i) = *(const float4*)(qb + i);
        }
    }
    __syncthreads();
    // ---- transpose U -> Qt[k][m] (one-time; conflicts acceptable) ----
    #pragma unroll
    for (int it = 0; it < 64; ++it) {
        int idx = tid + 128 * it;          // idx = m*256 + k
        Qt[(idx & 255) * QPAD + (idx >> 8)] = U[idx];
    }
    __syncthreads();

    const int mgrp = tid >> 5;             // 0..3
    const int lane = tid & 31;
    const int m0   = mgrp * 8;
    const int n0   = lane * 4;
    const int half = tid & 1;
    const int rowb = tid >> 1;             // 0..63

    const float* cb = ctx + (size_t)b * RD * DD + (size_t)r0 * DD + half * 4;

    uint64_t acc[32];                      // [4 m-pairs][8 n]
    #pragma unroll
    for (int i = 0; i < 32; ++i) acc[i] = 0ull;

    float4 st[4][2];
    // prefetch k-tile 0 and stage it into buffer 0
    #pragma unroll
    for (int j = 0; j < 4; ++j)
        #pragma unroll
        for (int c = 0; c < 2; ++c)
            st[j][c] = *(const float4*)(cb + (rowb + 64 * j) * DD + c * 8);
    {
        float* bp = U;
        #pragma unroll
        for (int j = 0; j < 4; ++j) {
            const int n = rowb + 64 * j;
            #pragma unroll
            for (int c = 0; c < 2; ++c) {
                const int kl = half * 4 + c * 8;
                bp[(kl + 0) * CPAD + n] = st[j][c].x;
                bp[(kl + 1) * CPAD + n] = st[j][c].y;
                bp[(kl + 2) * CPAD + n] = st[j][c].z;
                bp[(kl + 3) * CPAD + n] = st[j][c].w;
            }
        }
    }
    __syncthreads();

    for (int kt = 0; kt < DD / KT; ++kt) {
        const float* bp = U + (kt & 1) * (KT * CPAD);
        const bool more = (kt + 1 < DD / KT);

        // prefetch next tile to regs (latency hidden under compute)
        if (more) {
            const float* cn = cb + (kt + 1) * KT;
            #pragma unroll
            for (int j = 0; j < 4; ++j)
                #pragma unroll
                for (int c = 0; c < 2; ++c)
                    st[j][c] = *(const float4*)(cn + (rowb + 64 * j) * DD + c * 8);
        }

        // compute this tile
        const float* aq0 = Qt + kt * KT * QPAD;
        #pragma unroll
        for (int k = 0; k < KT; ++k) {
            const float* aq = aq0 + k * QPAD + m0;
            ulonglong2 A0 = *(const ulonglong2*)(aq);       // m-pairs (m0,m0+1),(m0+2,m0+3)
            ulonglong2 A1 = *(const ulonglong2*)(aq + 4);   // (m0+4..m0+7)
            float4 bv0 = *(const float4*)(bp + k * CPAD + n0);
            float4 bv1 = *(const float4*)(bp + k * CPAD + n0 + 128);
            uint64_t bd[8];
            bd[0] = pack_dup(bv0.x); bd[1] = pack_dup(bv0.y);
            bd[2] = pack_dup(bv0.z); bd[3] = pack_dup(bv0.w);
            bd[4] = pack_dup(bv1.x); bd[5] = pack_dup(bv1.y);
            bd[6] = pack_dup(bv1.z); bd[7] = pack_dup(bv1.w);
            #pragma unroll
            for (int t = 0; t < 8; ++t) {
                fma2(acc[0 * 8 + t], A0.x, bd[t]);
                fma2(acc[1 * 8 + t], A0.y, bd[t]);
                fma2(acc[2 * 8 + t], A1.x, bd[t]);
                fma2(acc[3 * 8 + t], A1.y, bd[t]);
            }
        }

        // stage next tile into the other buffer, then one barrier
        if (more) {
            float* np = U + ((kt + 1) & 1) * (KT * CPAD);
            #pragma unroll
            for (int j = 0; j < 4; ++j) {
                const int n = rowb + 64 * j;
                #pragma unroll
                for (int c = 0; c < 2; ++c) {
                    const int kl = half * 4 + c * 8;
                    np[(kl + 0) * CPAD + n] = st[j][c].x;
                    np[(kl + 1) * CPAD + n] = st[j][c].y;
                    np[(kl + 2) * CPAD + n] = st[j][c].z;
                    np[(kl + 3) * CPAD + n] = st[j][c].w;
                }
            }
            __syncthreads();
        }
    }

    // ---- epilogue: write scores to gmem (coalesced float4) ----
    float* ob = out + ((size_t)b * 32 + m0) * RD + r0;
    #pragma unroll
    for (int mp = 0; mp < 4; ++mp) {
        float4 la, ha, lb, hb;
        unpack2(acc[mp * 8 + 0], la.x, ha.x);
        unpack2(acc[mp * 8 + 1], la.y, ha.y);
        unpack2(acc[mp * 8 + 2], la.z, ha.z);
        unpack2(acc[mp * 8 + 3], la.w, ha.w);
        unpack2(acc[mp * 8 + 4], lb.x, hb.x);
        unpack2(acc[mp * 8 + 5], lb.y, hb.y);
        unpack2(acc[mp * 8 + 6], lb.z, hb.z);
        unpack2(acc[mp * 8 + 7], lb.w, hb.w);
        float* r_lo = ob + (size_t)(2 * mp) * RD;
        float* r_hi = ob + (size_t)(2 * mp + 1) * RD;
        *(float4*)(r_lo + n0)       = la;
        *(float4*)(r_lo + n0 + 128) = lb;
        *(float4*)(r_hi + n0)       = ha;
        *(float4*)(r_hi + n0 + 128) = hb;
    }
}

// ============ Pass 2: in-place sparsemax, register-resident rows ============
__global__ __launch_bounds__(256)
void sparsemax_kernel(float* __restrict__ out) {
    const int lane = threadIdx.x & 31;
    const size_t row = (size_t)blockIdx.x * 8 + (threadIdx.x >> 5);
    float4* rp = (float4*)(out + row * RD);

    float4 v[16];
    #pragma unroll
    for (int t = 0; t < 16; ++t) v[t] = rp[lane + 32 * t];

    // row max
    float vmax = -1e30f;
    #pragma unroll
    for (int t = 0; t < 16; ++t)
        vmax = fmaxf(vmax, fmaxf(fmaxf(v[t].x, v[t].y), fmaxf(v[t].z, v[t].w)));
    #pragma unroll
    for (int s = 16; s; s >>= 1)
        vmax = fmaxf(vmax, __shfl_xor_sync(0xffffffffu, vmax, s));

    // Newton from below on f(tau) = sum(relu(z - tau)) - 1 (convex PL, monotone)
    float tau = vmax - 1.0f;
    for (int it = 0; it < 48; ++it) {
        float S = 0.0f; int cnt = 0;
        #pragma unroll
        for (int t = 0; t < 16; ++t) {
            float d;
            d = v[t].x - tau; if (d > 0.0f) { S += d; cnt++; }
            d = v[t].y - tau; if (d > 0.0f) { S += d; cnt++; }
            d = v[t].z - tau; if (d > 0.0f) { S += d; cnt++; }
            d = v[t].w - tau; if (d > 0.0f) { S += d; cnt++; }
        }
        #pragma unroll
        for (int s = 16; s; s >>= 1) {
            S   += __shfl_xor_sync(0xffffffffu, S, s);
            cnt += __shfl_xor_sync(0xffffffffu, cnt, s);
        }
        if (cnt == 0) break;
        float delta = (S - 1.0f) / (float)cnt;
        if (!(delta > 1e-7f * fmaxf(fabsf(tau), 1.0f))) break;
        tau += delta;
    }

    #pragma unroll
    for (int t = 0; t < 16; ++t) {
        float4 o;
        o.x = fmaxf(v[t].x - tau, 0.0f);
        o.y = fmaxf(v[t].y - tau, 0.0f);
        o.z = fmaxf(v[t].z - tau, 0.0f);
        o.w = fmaxf(v[t].w - tau, 0.0f);
        rp[lane + 32 * t] = o;
    }
}

extern "C" void kernel_launch(void* const* d_in, const int* in_sizes, int n_in,
                              void* d_out, int out_size) {
    (void)n_in; (void)out_size;
    const float* q   = (const float*)d_in[0];
    const float* ctx = (const float*)d_in[1];
    float* out = (float*)d_out;

    const int B = in_sizes[0] / (32 * DD);   // 512

    cudaFuncSetAttribute(gemm_kernel,
                         cudaFuncAttributeMaxDynamicSharedMemorySize, P1_SMEM_BYTES);

    dim3 g1(RD / NT, B);                     // 8 x 512 CTAs
    gemm_kernel<<<g1, 128, P1_SMEM_BYTES>>>(q, ctx, out);

    const int rows = B * 32;                 // 16384
    sparsemax_kernel<<<rows / 8, 256>>>(out);
}

// round 7
// speedup vs baseline: 1.7141x; 1.0068x over previous
#include <cuda_runtime.h>
#include <cstdint>

// query [512,32,256], context [512,2048,256], out [16384,2048] fp32.
#define DD   256
#define RD   2048
#define NT   256      // N-chunk per CTA (pass 1)
#define KT   16       // K tile
#define CPAD 260      // padded transposed C row (conflict-free transpose staging)
#define QPAD 36       // padded Qt row (16B-aligned rows: 36*4=144B)

#define QT_FLOATS (DD * QPAD)          // 9216
#define U_FLOATS  (2 * KT * CPAD)      // 8320  (also holds 8192-float Q staging)
#define P1_SMEM_BYTES ((QT_FLOATS + U_FLOATS) * 4)   // 70144 B -> 3 CTAs/SM

__device__ __forceinline__ uint64_t pack_dup(float x) {
    uint64_t r;
    asm("mov.b64 %0, {%1, %1};" : "=l"(r) : "f"(x));
    return r;
}
__device__ __forceinline__ void fma2(uint64_t& d, uint64_t a, uint64_t b) {
    asm("fma.rn.f32x2 %0, %1, %2, %0;" : "+l"(d) : "l"(a), "l"(b));
}
__device__ __forceinline__ void unpack2(uint64_t v, float& lo, float& hi) {
    asm("mov.b64 {%0, %1}, %2;" : "=f"(lo), "=f"(hi) : "l"(v));
}

// ===================== Pass 1: scores = Q @ C^T -> out ======================
// CTA: 128 threads, tile 32m x 256n, thread tile 16m x 4n (m-paired f32x2).
__global__ __launch_bounds__(128, 3)
void gemm_kernel(const float* __restrict__ q,
                 const float* __restrict__ ctx,
                 float* __restrict__ out) {
    extern __shared__ float smem[];
    float* Qt = smem;              // [DD][QPAD] : Qt[k][m]
    float* U  = smem + QT_FLOATS;  // union: Q staging (8192 f) / C double buffer

    const int tid = threadIdx.x;
    const int b   = blockIdx.y;
    const int r0  = blockIdx.x * NT;

    // ---- stage Q [32][256] coalesced into U ----
    {
        const float* qb = q + (size_t)b * 32 * DD;
        #pragma unroll
        for (int it = 0; it < 16; ++it) {
            int i = (tid + 128 * it) * 4;
            *(float4*)(U + i) = *(const float4*)(qb + i);
        }
    }
    __syncthreads();
    // ---- transpose U -> Qt[k][m] (one-time) ----
    #pragma unroll
    for (int it = 0; it < 64; ++it) {
        int idx = tid + 128 * it;          // idx = m*256 + k
        Qt[(idx & 255) * QPAD + (idx >> 8)] = U[idx];
    }
    __syncthreads();

    const int mgrp = tid >> 6;             // 0..1  (whole warp same mgrp -> A broadcast)
    const int m0   = mgrp * 16;
    const int n0   = (tid & 63) * 4;       // 4 contiguous n per thread
    const int half = tid & 1;
    const int rowb = tid >> 1;             // 0..63

    const float* cb = ctx + (size_t)b * RD * DD + (size_t)r0 * DD + half * 4;

    uint64_t acc[32];                      // [8 m-pairs][4 n]
    #pragma unroll
    for (int i = 0; i < 32; ++i) acc[i] = 0ull;

    float4 st[4][2];
    // prefetch k-tile 0 and stage it into buffer 0
    #pragma unroll
    for (int j = 0; j < 4; ++j)
        #pragma unroll
        for (int c = 0; c < 2; ++c)
            st[j][c] = *(const float4*)(cb + (rowb + 64 * j) * DD + c * 8);
    {
        float* bp = U;
        #pragma unroll
        for (int j = 0; j < 4; ++j) {
            const int n = rowb + 64 * j;
            #pragma unroll
            for (int c = 0; c < 2; ++c) {
                const int kl = half * 4 + c * 8;
                bp[(kl + 0) * CPAD + n] = st[j][c].x;
                bp[(kl + 1) * CPAD + n] = st[j][c].y;
                bp[(kl + 2) * CPAD + n] = st[j][c].z;
                bp[(kl + 3) * CPAD + n] = st[j][c].w;
            }
        }
    }
    __syncthreads();

    for (int kt = 0; kt < DD / KT; ++kt) {
        const float* bp = U + (kt & 1) * (KT * CPAD);
        const bool more = (kt + 1 < DD / KT);

        // prefetch next tile to regs (latency hidden under compute)
        if (more) {
            const float* cn = cb + (kt + 1) * KT;
            #pragma unroll
            for (int j = 0; j < 4; ++j)
                #pragma unroll
                for (int c = 0; c < 2; ++c)
                    st[j][c] = *(const float4*)(cn + (rowb + 64 * j) * DD + c * 8);
        }

        // compute this tile
        const float* aq0 = Qt + kt * KT * QPAD + m0;
        #pragma unroll
        for (int k = 0; k < KT; ++k) {
            const float* aq = aq0 + k * QPAD;
            // 16 m-values as 8 f32x2 pairs (broadcast loads, conflict-free)
            ulonglong2 A0 = *(const ulonglong2*)(aq);       // (m0..m0+3)
            ulonglong2 A1 = *(const ulonglong2*)(aq + 4);   // (m0+4..m0+7)
            ulonglong2 A2 = *(const ulonglong2*)(aq + 8);   // (m0+8..m0+11)
            ulonglong2 A3 = *(const ulonglong2*)(aq + 12);  // (m0+12..m0+15)
            float4 bv = *(const float4*)(bp + k * CPAD + n0);
            uint64_t b0 = pack_dup(bv.x), b1 = pack_dup(bv.y);
            uint64_t b2 = pack_dup(bv.z), b3 = pack_dup(bv.w);
            fma2(acc[ 0], A0.x, b0); fma2(acc[ 1], A0.x, b1);
            fma2(acc[ 2], A0.x, b2); fma2(acc[ 3], A0.x, b3);
            fma2(acc[ 4], A0.y, b0); fma2(acc[ 5], A0.y, b1);
            fma2(acc[ 6], A0.y, b2); fma2(acc[ 7], A0.y, b3);
            fma2(acc[ 8], A1.x, b0); fma2(acc[ 9], A1.x, b1);
            fma2(acc[10], A1.x, b2); fma2(acc[11], A1.x, b3);
            fma2(acc[12], A1.y, b0); fma2(acc[13], A1.y, b1);
            fma2(acc[14], A1.y, b2); fma2(acc[15], A1.y, b3);
            fma2(acc[16], A2.x, b0); fma2(acc[17], A2.x, b1);
            fma2(acc[18], A2.x, b2); fma2(acc[19], A2.x, b3);
            fma2(acc[20], A2.y, b0); fma2(acc[21], A2.y, b1);
            fma2(acc[22], A2.y, b2); fma2(acc[23], A2.y, b3);
            fma2(acc[24], A3.x, b0); fma2(acc[25], A3.x, b1);
            fma2(acc[26], A3.x, b2); fma2(acc[27], A3.x, b3);
            fma2(acc[28], A3.y, b0); fma2(acc[29], A3.y, b1);
            fma2(acc[30], A3.y, b2); fma2(acc[31], A3.y, b3);
        }

        // stage next tile into the other buffer, then one barrier
        if (more) {
            float* np = U + ((kt + 1) & 1) * (KT * CPAD);
            #pragma unroll
            for (int j = 0; j < 4; ++j) {
                const int n = rowb + 64 * j;
                #pragma unroll
                for (int c = 0; c < 2; ++c) {
                    const int kl = half * 4 + c * 8;
                    np[(kl + 0) * CPAD + n] = st[j][c].x;
                    np[(kl + 1) * CPAD + n] = st[j][c].y;
                    np[(kl + 2) * CPAD + n] = st[j][c].z;
                    np[(kl + 3) * CPAD + n] = st[j][c].w;
                }
            }
            __syncthreads();
        }
    }

    // ---- epilogue: write scores to gmem (coalesced float4) ----
    float* ob = out + ((size_t)b * 32 + m0) * RD + r0 + n0;
    #pragma unroll
    for (int mp = 0; mp < 8; ++mp) {
        float4 lo, hi;
        unpack2(acc[mp * 4 + 0], lo.x, hi.x);
        unpack2(acc[mp * 4 + 1], lo.y, hi.y);
        unpack2(acc[mp * 4 + 2], lo.z, hi.z);
        unpack2(acc[mp * 4 + 3], lo.w, hi.w);
        *(float4*)(ob + (size_t)(2 * mp)     * RD) = lo;
        *(float4*)(ob + (size_t)(2 * mp + 1) * RD) = hi;
    }
}

// ============ Pass 2: in-place sparsemax, register-resident rows ============
__global__ __launch_bounds__(256)
void sparsemax_kernel(float* __restrict__ out) {
    const int lane = threadIdx.x & 31;
    const size_t row = (size_t)blockIdx.x * 8 + (threadIdx.x >> 5);
    float4* rp = (float4*)(out + row * RD);

    float4 v[16];
    #pragma unroll
    for (int t = 0; t < 16; ++t) v[t] = rp[lane + 32 * t];

    // row max
    float vmax = -1e30f;
    #pragma unroll
    for (int t = 0; t < 16; ++t)
        vmax = fmaxf(vmax, fmaxf(fmaxf(v[t].x, v[t].y), fmaxf(v[t].z, v[t].w)));
    #pragma unroll
    for (int s = 16; s; s >>= 1)
        vmax = fmaxf(vmax, __shfl_xor_sync(0xffffffffu, vmax, s));

    // Newton from below on f(tau) = sum(relu(z - tau)) - 1 (convex PL, monotone)
    float tau = vmax - 1.0f;
    for (int it = 0; it < 48; ++it) {
        float S = 0.0f; int cnt = 0;
        #pragma unroll
        for (int t = 0; t < 16; ++t) {
            float d;
            d = v[t].x - tau; if (d > 0.0f) { S += d; cnt++; }
            d = v[t].y - tau; if (d > 0.0f) { S += d; cnt++; }
            d = v[t].z - tau; if (d > 0.0f) { S += d; cnt++; }
            d = v[t].w - tau; if (d > 0.0f) { S += d; cnt++; }
        }
        #pragma unroll
        for (int s = 16; s; s >>= 1) {
            S   += __shfl_xor_sync(0xffffffffu, S, s);
            cnt += __shfl_xor_sync(0xffffffffu, cnt, s);
        }
        if (cnt == 0) break;
        float delta = (S - 1.0f) / (float)cnt;
        if (!(delta > 1e-7f * fmaxf(fabsf(tau), 1.0f))) break;
        tau += delta;
    }

    #pragma unroll
    for (int t = 0; t < 16; ++t) {
        float4 o;
        o.x = fmaxf(v[t].x - tau, 0.0f);
        o.y = fmaxf(v[t].y - tau, 0.0f);
        o.z = fmaxf(v[t].z - tau, 0.0f);
        o.w = fmaxf(v[t].w - tau, 0.0f);
        rp[lane + 32 * t] = o;
    }
}

extern "C" void kernel_launch(void* const* d_in, const int* in_sizes, int n_in,
                              void* d_out, int out_size) {
    (void)n_in; (void)out_size;
    const float* q   = (const float*)d_in[0];
    const float* ctx = (const float*)d_in[1];
    float* out = (float*)d_out;

    const int B = in_sizes[0] / (32 * DD);   // 512

    cudaFuncSetAttribute(gemm_kernel,
                         cudaFuncAttributeMaxDynamicSharedMemorySize, P1_SMEM_BYTES);

    dim3 g1(RD / NT, B);                     // 8 x 512 CTAs
    gemm_kernel<<<g1, 128, P1_SMEM_BYTES>>>(q, ctx, out);

    const int rows = B * 32;                 // 16384
    sparsemax_kernel<<<rows / 8, 256>>>(out);
}